// round 6
// baseline (speedup 1.0000x reference)
#include <cuda_runtime.h>
#include <cuda_fp16.h>
#include <stdint.h>

#define BB 4
#define SS 1024
#define HH 32
#define KVHH 8
#define DD 128
#define QTILE 64
#define KTILE 32
#define WIN 512
#define NT 128

// fp16 smem tiles, 256B rows (128 halves), 16B-chunk XOR swizzle
#define QBYTES (64 * 256)                   // 16KB (prologue only)
#define KBYTES (32 * 256)                   // 8KB per K/V buffer
#define SMEM_BYTES (QBYTES + 4 * KBYTES)    // 48KB

__device__ __forceinline__ uint32_t swadr(uint32_t base, int row, int chunk) {
    return base + row * 256 + ((chunk ^ (row & 7)) << 4);
}
__device__ __forceinline__ float tanh_fast(float x) {
    float y; asm("tanh.approx.f32 %0, %1;" : "=f"(y) : "f"(x)); return y;
}
__device__ __forceinline__ float ex2(float x) {
    float y; asm("ex2.approx.f32 %0, %1;" : "=f"(y) : "f"(x)); return y;
}
__device__ __forceinline__ uint32_t pk(float lo, float hi) {
    __half2 h = __floats2half2_rn(lo, hi);
    return *(uint32_t*)&h;
}
__device__ __forceinline__ void ldsm4(uint32_t& r0, uint32_t& r1, uint32_t& r2, uint32_t& r3, uint32_t a) {
    asm volatile("ldmatrix.sync.aligned.m8n8.x4.shared.b16 {%0,%1,%2,%3},[%4];"
                 : "=r"(r0), "=r"(r1), "=r"(r2), "=r"(r3) : "r"(a));
}
__device__ __forceinline__ void ldsm4t(uint32_t& r0, uint32_t& r1, uint32_t& r2, uint32_t& r3, uint32_t a) {
    asm volatile("ldmatrix.sync.aligned.m8n8.x4.trans.shared.b16 {%0,%1,%2,%3},[%4];"
                 : "=r"(r0), "=r"(r1), "=r"(r2), "=r"(r3) : "r"(a));
}
__device__ __forceinline__ void mma16(float* d, uint32_t a0, uint32_t a1, uint32_t a2, uint32_t a3,
                                      uint32_t b0, uint32_t b1) {
    asm volatile(
        "mma.sync.aligned.m16n8k16.row.col.f32.f16.f16.f32 "
        "{%0,%1,%2,%3}, {%4,%5,%6,%7}, {%8,%9}, {%0,%1,%2,%3};"
        : "+f"(d[0]), "+f"(d[1]), "+f"(d[2]), "+f"(d[3])
        : "r"(a0), "r"(a1), "r"(a2), "r"(a3), "r"(b0), "r"(b1));
}

__global__ __launch_bounds__(NT, 2)
void attn_kernel(const float* __restrict__ q,
                 const float* __restrict__ kk,
                 const float* __restrict__ vv,
                 float* __restrict__ out)
{
    extern __shared__ char smraw[];
    uint32_t smb;
    asm("{ .reg .u64 t; cvta.to.shared.u64 t, %1; cvt.u32.u64 %0, t; }" : "=r"(smb) : "l"(smraw));
    const uint32_t Qb = smb, Kb = smb + QBYTES, Vb = Kb + 2 * KBYTES;

    const int qt = blockIdx.x, h = blockIdx.y, b = blockIdx.z;
    const int kvh = h >> 2;
    const int q0  = qt * QTILE;
    const int tid = threadIdx.x, lane = tid & 31, w = tid >> 5;
    const int g = lane >> 2, tg = lane & 3;

    // loader coords: 8-float (2xfloat4) unit at (row idx>>4, chunk idx&15)
    const int lr = tid >> 4;   // 0..7
    const int lc = tid & 15;   // chunk

    // ldmatrix lane coords
    const int rowA  = 16 * w + (lane & 7) + 8 * ((lane >> 3) & 1);
    const int cA    = lane >> 4;
    const int rowB  = (lane & 7) + 8 * (lane >> 4);
    const int cB    = (lane >> 3) & 1;
    const int rowV_ = (lane & 7) + 8 * ((lane >> 3) & 1);
    const int cV    = lane >> 4;

    const int lo = (q0 - WIN + 1 > 0) ? ((q0 - WIN + 1) >> 5) : 0;   // key-tile units of 32
    const int hi = (q0 + QTILE - 1) >> 5;

    const float qscale = 0.08838834764831843f * 0.02f;  // 1/sqrt(128) / 50 (softcap folded)
    const float LOG2E  = 1.4426950408889634f;

    float4 kr[8], vr[8];

    // ---- prologue: LDG K/V tile 'lo' ----
    {
        const int j0 = lo * KTILE;
        #pragma unroll
        for (int it = 0; it < 4; it++) {
            const int r = lr + 8 * it;                  // 0..31
            const float* kp = kk + ((size_t)((b * SS + j0 + r) * KVHH + kvh)) * DD + 8 * lc;
            const float* vp = vv + ((size_t)((b * SS + j0 + r) * KVHH + kvh)) * DD + 8 * lc;
            kr[2 * it]     = *(const float4*)kp;
            kr[2 * it + 1] = *(const float4*)(kp + 4);
            vr[2 * it]     = *(const float4*)vp;
            vr[2 * it + 1] = *(const float4*)(vp + 4);
        }
    }
    // ---- Q: LDG -> scale -> fp16 -> swizzled STS ----
    #pragma unroll
    for (int it = 0; it < 8; it++) {
        const int idx = tid + NT * it;
        const int r = idx >> 4, c8 = idx & 15;          // r 0..63
        const float* qp = q + ((size_t)((b * SS + q0 + r) * HH + h)) * DD + 8 * c8;
        float4 f0 = *(const float4*)qp;
        float4 f1 = *(const float4*)(qp + 4);
        uint4 u;
        u.x = pk(f0.x * qscale, f0.y * qscale);
        u.y = pk(f0.z * qscale, f0.w * qscale);
        u.z = pk(f1.x * qscale, f1.y * qscale);
        u.w = pk(f1.z * qscale, f1.w * qscale);
        asm volatile("st.shared.v4.b32 [%0], {%1,%2,%3,%4};"
                     :: "r"(swadr(Qb, r, c8)), "r"(u.x), "r"(u.y), "r"(u.z), "r"(u.w));
    }
    // ---- store K/V tile lo into buffer 0 ----
    #pragma unroll
    for (int it = 0; it < 4; it++) {
        const int r = lr + 8 * it;
        uint4 uk, uv;
        uk.x = pk(kr[2*it].x, kr[2*it].y);     uk.y = pk(kr[2*it].z, kr[2*it].w);
        uk.z = pk(kr[2*it+1].x, kr[2*it+1].y); uk.w = pk(kr[2*it+1].z, kr[2*it+1].w);
        uv.x = pk(vr[2*it].x, vr[2*it].y);     uv.y = pk(vr[2*it].z, vr[2*it].w);
        uv.z = pk(vr[2*it+1].x, vr[2*it+1].y); uv.w = pk(vr[2*it+1].z, vr[2*it+1].w);
        asm volatile("st.shared.v4.b32 [%0], {%1,%2,%3,%4};"
                     :: "r"(swadr(Kb, r, lc)), "r"(uk.x), "r"(uk.y), "r"(uk.z), "r"(uk.w));
        asm volatile("st.shared.v4.b32 [%0], {%1,%2,%3,%4};"
                     :: "r"(swadr(Vb, r, lc)), "r"(uv.x), "r"(uv.y), "r"(uv.z), "r"(uv.w));
    }
    __syncthreads();

    // ---- Q fragments -> registers (once) ----
    uint32_t qf[8][4];
    #pragma unroll
    for (int i = 0; i < 8; i++)
        ldsm4(qf[i][0], qf[i][1], qf[i][2], qf[i][3], swadr(Qb, rowA, 2 * i + cA));

    float o[16][4];
    #pragma unroll
    for (int t = 0; t < 16; t++) { o[t][0] = 0.f; o[t][1] = 0.f; o[t][2] = 0.f; o[t][3] = 0.f; }
    float m0 = -1e30f, m1 = -1e30f, l0 = 0.f, l1 = 0.f;

    const int rlo = q0 + 16 * w, rhi = rlo + 15;
    const int ig0 = rlo + g, ig1 = ig0 + 8;

    for (int kt = lo; kt <= hi; kt++) {
        const int cur = (kt - lo) & 1;
        // prefetch next K/V tile into regs
        if (kt < hi) {
            const int j0n = (kt + 1) * KTILE;
            #pragma unroll
            for (int it = 0; it < 4; it++) {
                const int r = lr + 8 * it;
                const float* kp = kk + ((size_t)((b * SS + j0n + r) * KVHH + kvh)) * DD + 8 * lc;
                const float* vp = vv + ((size_t)((b * SS + j0n + r) * KVHH + kvh)) * DD + 8 * lc;
                kr[2 * it]     = *(const float4*)kp;
                kr[2 * it + 1] = *(const float4*)(kp + 4);
                vr[2 * it]     = *(const float4*)vp;
                vr[2 * it + 1] = *(const float4*)(vp + 4);
            }
        }

        const int j0 = kt * KTILE;
        const bool active = (j0 <= rhi) && (j0 + KTILE - 1 >= rlo - WIN + 1);
        if (active) {
            const uint32_t Kc = Kb + cur * KBYTES;
            const uint32_t Vc = Vb + cur * KBYTES;
            const bool masked = (j0 + KTILE - 1 > rlo) || (rhi - j0 >= WIN);

            // ---- S = Q K^T : 8 k-steps, n=32 ----
            float s[4][4];
            #pragma unroll
            for (int t = 0; t < 4; t++) { s[t][0] = 0.f; s[t][1] = 0.f; s[t][2] = 0.f; s[t][3] = 0.f; }
            #pragma unroll
            for (int i = 0; i < 8; i++) {
                #pragma unroll
                for (int p = 0; p < 2; p++) {
                    uint32_t b0, b1, b2, b3;
                    ldsm4(b0, b1, b2, b3, swadr(Kc, rowB + 16 * p, 2 * i + cB));
                    mma16(s[2 * p],     qf[i][0], qf[i][1], qf[i][2], qf[i][3], b0, b1);
                    mma16(s[2 * p + 1], qf[i][0], qf[i][1], qf[i][2], qf[i][3], b2, b3);
                }
            }

            // ---- softcap (+ mask only on edge tiles) + online softmax ----
            float rmax0 = -1e30f, rmax1 = -1e30f;
            if (masked) {
                #pragma unroll
                for (int t = 0; t < 4; t++) {
                    const int jg = j0 + 8 * t + 2 * tg;
                    float v0 = 50.f * tanh_fast(s[t][0]);
                    float v1 = 50.f * tanh_fast(s[t][1]);
                    float v2 = 50.f * tanh_fast(s[t][2]);
                    float v3 = 50.f * tanh_fast(s[t][3]);
                    bool ok0 = (jg     <= ig0) && (ig0 - jg     < WIN);
                    bool ok1 = (jg + 1 <= ig0) && (ig0 - jg - 1 < WIN);
                    bool ok2 = (jg     <= ig1) && (ig1 - jg     < WIN);
                    bool ok3 = (jg + 1 <= ig1) && (ig1 - jg - 1 < WIN);
                    s[t][0] = ok0 ? v0 : -1e30f;
                    s[t][1] = ok1 ? v1 : -1e30f;
                    s[t][2] = ok2 ? v2 : -1e30f;
                    s[t][3] = ok3 ? v3 : -1e30f;
                    rmax0 = fmaxf(rmax0, fmaxf(s[t][0], s[t][1]));
                    rmax1 = fmaxf(rmax1, fmaxf(s[t][2], s[t][3]));
                }
            } else {
                #pragma unroll
                for (int t = 0; t < 4; t++) {
                    s[t][0] = 50.f * tanh_fast(s[t][0]);
                    s[t][1] = 50.f * tanh_fast(s[t][1]);
                    s[t][2] = 50.f * tanh_fast(s[t][2]);
                    s[t][3] = 50.f * tanh_fast(s[t][3]);
                    rmax0 = fmaxf(rmax0, fmaxf(s[t][0], s[t][1]));
                    rmax1 = fmaxf(rmax1, fmaxf(s[t][2], s[t][3]));
                }
            }
            rmax0 = fmaxf(rmax0, __shfl_xor_sync(0xffffffffu, rmax0, 1));
            rmax0 = fmaxf(rmax0, __shfl_xor_sync(0xffffffffu, rmax0, 2));
            rmax1 = fmaxf(rmax1, __shfl_xor_sync(0xffffffffu, rmax1, 1));
            rmax1 = fmaxf(rmax1, __shfl_xor_sync(0xffffffffu, rmax1, 2));

            const float m0n = fmaxf(m0, rmax0);
            const float m1n = fmaxf(m1, rmax1);
            const float al0 = ex2((m0 - m0n) * LOG2E);
            const float al1 = ex2((m1 - m1n) * LOG2E);
            m0 = m0n; m1 = m1n;

            float ls0 = 0.f, ls1 = 0.f;
            if (masked) {
                #pragma unroll
                for (int t = 0; t < 4; t++) {
                    float p0 = (s[t][0] > -1e29f) ? ex2((s[t][0] - m0n) * LOG2E) : 0.f;
                    float p1 = (s[t][1] > -1e29f) ? ex2((s[t][1] - m0n) * LOG2E) : 0.f;
                    float p2 = (s[t][2] > -1e29f) ? ex2((s[t][2] - m1n) * LOG2E) : 0.f;
                    float p3 = (s[t][3] > -1e29f) ? ex2((s[t][3] - m1n) * LOG2E) : 0.f;
                    s[t][0] = p0; s[t][1] = p1; s[t][2] = p2; s[t][3] = p3;
                    ls0 += p0 + p1; ls1 += p2 + p3;
                }
            } else {
                #pragma unroll
                for (int t = 0; t < 4; t++) {
                    float p0 = ex2((s[t][0] - m0n) * LOG2E);
                    float p1 = ex2((s[t][1] - m0n) * LOG2E);
                    float p2 = ex2((s[t][2] - m1n) * LOG2E);
                    float p3 = ex2((s[t][3] - m1n) * LOG2E);
                    s[t][0] = p0; s[t][1] = p1; s[t][2] = p2; s[t][3] = p3;
                    ls0 += p0 + p1; ls1 += p2 + p3;
                }
            }
            ls0 += __shfl_xor_sync(0xffffffffu, ls0, 1);
            ls0 += __shfl_xor_sync(0xffffffffu, ls0, 2);
            ls1 += __shfl_xor_sync(0xffffffffu, ls1, 1);
            ls1 += __shfl_xor_sync(0xffffffffu, ls1, 2);
            l0 = l0 * al0 + ls0;
            l1 = l1 * al1 + ls1;

            #pragma unroll
            for (int t = 0; t < 16; t++) {
                o[t][0] *= al0; o[t][1] *= al0; o[t][2] *= al1; o[t][3] *= al1;
            }

            // ---- PV: 2 k-steps of 16, A from S regs, B via ldmatrix.trans ----
            #pragma unroll
            for (int u = 0; u < 2; u++) {
                const uint32_t a0 = pk(s[2*u][0],   s[2*u][1]);
                const uint32_t a1 = pk(s[2*u][2],   s[2*u][3]);
                const uint32_t a2 = pk(s[2*u+1][0], s[2*u+1][1]);
                const uint32_t a3 = pk(s[2*u+1][2], s[2*u+1][3]);
                #pragma unroll
                for (int p = 0; p < 8; p++) {
                    uint32_t b0, b1, b2, b3;
                    ldsm4t(b0, b1, b2, b3, swadr(Vc, 16 * u + rowV_, 2 * p + cV));
                    mma16(o[2 * p],     a0, a1, a2, a3, b0, b1);
                    mma16(o[2 * p + 1], a0, a1, a2, a3, b2, b3);
                }
            }
        }

        // ---- store prefetched tile into other buffer ----
        if (kt < hi) {
            const uint32_t Kn = Kb + (cur ^ 1) * KBYTES;
            const uint32_t Vn = Vb + (cur ^ 1) * KBYTES;
            #pragma unroll
            for (int it = 0; it < 4; it++) {
                const int r = lr + 8 * it;
                uint4 uk, uv;
                uk.x = pk(kr[2*it].x, kr[2*it].y);     uk.y = pk(kr[2*it].z, kr[2*it].w);
                uk.z = pk(kr[2*it+1].x, kr[2*it+1].y); uk.w = pk(kr[2*it+1].z, kr[2*it+1].w);
                uv.x = pk(vr[2*it].x, vr[2*it].y);     uv.y = pk(vr[2*it].z, vr[2*it].w);
                uv.z = pk(vr[2*it+1].x, vr[2*it+1].y); uv.w = pk(vr[2*it+1].z, vr[2*it+1].w);
                asm volatile("st.shared.v4.b32 [%0], {%1,%2,%3,%4};"
                             :: "r"(swadr(Kn, r, lc)), "r"(uk.x), "r"(uk.y), "r"(uk.z), "r"(uk.w));
                asm volatile("st.shared.v4.b32 [%0], {%1,%2,%3,%4};"
                             :: "r"(swadr(Vn, r, lc)), "r"(uv.x), "r"(uv.y), "r"(uv.z), "r"(uv.w));
            }
        }
        __syncthreads();
    }

    // ---- write output ----
    const float inv0 = 1.f / l0;
    const float inv1 = 1.f / l1;
    const size_t base0 = ((size_t)((b * SS + ig0) * HH + h)) * DD;
    const size_t base1 = ((size_t)((b * SS + ig1) * HH + h)) * DD;
    #pragma unroll
    for (int t = 0; t < 16; t++) {
        const int col = 8 * t + 2 * tg;
        *(float2*)&out[base0 + col] = make_float2(o[t][0] * inv0, o[t][1] * inv0);
        *(float2*)&out[base1 + col] = make_float2(o[t][2] * inv1, o[t][3] * inv1);
    }
}

extern "C" void kernel_launch(void* const* d_in, const int* in_sizes, int n_in,
                              void* d_out, int out_size)
{
    const float* q = (const float*)d_in[0];   // query  [4096,32,128]
    const float* k = (const float*)d_in[1];   // key    [4096, 8,128]
    const float* v = (const float*)d_in[2];   // value  [4096, 8,128]
    // d_in[3..5] (caches + block table) do not affect the output: the cache
    // write-then-gather of the same permutation blocks returns key/value unchanged.
    float* out = (float*)d_out;

    cudaFuncSetAttribute(attn_kernel,
                         cudaFuncAttributeMaxDynamicSharedMemorySize,
                         SMEM_BYTES);

    dim3 grid(SS / QTILE, HH, BB);   // 16 x 32 x 4 = 2048 blocks
    attn_kernel<<<grid, NT, SMEM_BYTES>>>(q, k, v, out);
}

// round 7
// speedup vs baseline: 1.9472x; 1.9472x over previous
#include <cuda_runtime.h>
#include <cuda_fp16.h>
#include <stdint.h>

#define BB 4
#define SS 1024
#define HH 32
#define KVHH 8
#define DD 128
#define QTILE 128
#define KTILE 64
#define WIN 512
#define NT 256

#define KV_ELEMS (BB * SS * KVHH * DD)   // 4194304

// fp16 K/V scratch (pre-converted by convert_kv kernel)
__device__ __half KH[KV_ELEMS];
__device__ __half VH[KV_ELEMS];

// smem: Q 128x256B = 32KB, ring of 3 x (K 16KB + V 16KB) = 96KB -> 128KB
#define QBYTES (128 * 256)
#define KBYTES (64 * 256)
#define SMEM_BYTES (QBYTES + 6 * KBYTES)

__device__ __forceinline__ uint32_t swadr(uint32_t base, int row, int chunk) {
    return base + row * 256 + ((chunk ^ (row & 7)) << 4);
}
__device__ __forceinline__ float tanh_fast(float x) {
    float y; asm("tanh.approx.f32 %0, %1;" : "=f"(y) : "f"(x)); return y;
}
__device__ __forceinline__ float ex2(float x) {
    float y; asm("ex2.approx.f32 %0, %1;" : "=f"(y) : "f"(x)); return y;
}
__device__ __forceinline__ uint32_t pk(float lo, float hi) {
    __half2 h = __floats2half2_rn(lo, hi);
    return *(uint32_t*)&h;
}
__device__ __forceinline__ void ldsm4(uint32_t& r0, uint32_t& r1, uint32_t& r2, uint32_t& r3, uint32_t a) {
    asm volatile("ldmatrix.sync.aligned.m8n8.x4.shared.b16 {%0,%1,%2,%3},[%4];"
                 : "=r"(r0), "=r"(r1), "=r"(r2), "=r"(r3) : "r"(a));
}
__device__ __forceinline__ void ldsm4t(uint32_t& r0, uint32_t& r1, uint32_t& r2, uint32_t& r3, uint32_t a) {
    asm volatile("ldmatrix.sync.aligned.m8n8.x4.trans.shared.b16 {%0,%1,%2,%3},[%4];"
                 : "=r"(r0), "=r"(r1), "=r"(r2), "=r"(r3) : "r"(a));
}
__device__ __forceinline__ void mma16(float* d, uint32_t a0, uint32_t a1, uint32_t a2, uint32_t a3,
                                      uint32_t b0, uint32_t b1) {
    asm volatile(
        "mma.sync.aligned.m16n8k16.row.col.f32.f16.f16.f32 "
        "{%0,%1,%2,%3}, {%4,%5,%6,%7}, {%8,%9}, {%0,%1,%2,%3};"
        : "+f"(d[0]), "+f"(d[1]), "+f"(d[2]), "+f"(d[3])
        : "r"(a0), "r"(a1), "r"(a2), "r"(a3), "r"(b0), "r"(b1));
}
__device__ __forceinline__ void cpa16(uint32_t dst, const __half* src) {
    asm volatile("cp.async.cg.shared.global [%0], [%1], 16;" :: "r"(dst), "l"(src));
}

// ---- pre-pass: fp32 -> fp16 (round-to-nearest) for K and V ----
__global__ __launch_bounds__(256, 8)
void convert_kv(const float* __restrict__ k, const float* __restrict__ v) {
    const int i = (blockIdx.x * 256 + threadIdx.x) * 8;
    float4 a = *(const float4*)&k[i];
    float4 b = *(const float4*)&k[i + 4];
    uint4 u;
    u.x = pk(a.x, a.y); u.y = pk(a.z, a.w); u.z = pk(b.x, b.y); u.w = pk(b.z, b.w);
    *(uint4*)&KH[i] = u;
    a = *(const float4*)&v[i];
    b = *(const float4*)&v[i + 4];
    u.x = pk(a.x, a.y); u.y = pk(a.z, a.w); u.z = pk(b.x, b.y); u.w = pk(b.z, b.w);
    *(uint4*)&VH[i] = u;
}

__global__ __launch_bounds__(NT, 1)
void attn_kernel(const float* __restrict__ q, float* __restrict__ out)
{
    extern __shared__ char smraw[];
    uint32_t smb;
    asm("{ .reg .u64 t; cvta.to.shared.u64 t, %1; cvt.u32.u64 %0, t; }" : "=r"(smb) : "l"(smraw));
    const uint32_t Qb = smb, Rb = smb + QBYTES;   // ring base

    const int qt = blockIdx.x, h = blockIdx.y, b = blockIdx.z;
    const int kvh = h >> 2;
    const int q0  = qt * QTILE;
    const int tid = threadIdx.x, lane = tid & 31, w = tid >> 5;
    const int g = lane >> 2, tg = lane & 3;

    const int lr = tid >> 4;   // 0..15
    const int lc = tid & 15;   // chunk 0..15

    const int rowA  = 16 * w + (lane & 7) + 8 * ((lane >> 3) & 1);
    const int cA    = lane >> 4;
    const int rowB  = (lane & 7) + 8 * (lane >> 4);
    const int cB    = (lane >> 3) & 1;
    const int rowV_ = (lane & 7) + 8 * ((lane >> 3) & 1);
    const int cV    = lane >> 4;

    const int lo = (q0 - WIN + 1 > 0) ? ((q0 - WIN + 1) >> 6) : 0;
    const int hi = (q0 + QTILE - 1) >> 6;

    const float qscale = 0.08838834764831843f * 0.02f;   // (1/sqrt(128)) / 50
    const float LOG2E  = 1.4426950408889634f;

    // issue cp.async for tile kt into ring slot (kt-lo)%3
    auto issue_tile = [&](int kt) {
        const int j0 = kt * KTILE;
        const uint32_t Kd = Rb + ((kt - lo) % 3) * 2 * KBYTES;
        const uint32_t Vd = Kd + KBYTES;
        const __half* kp = KH + ((size_t)((b * SS + j0 + lr) * KVHH + kvh)) * DD + 8 * lc;
        const __half* vp = VH + ((size_t)((b * SS + j0 + lr) * KVHH + kvh)) * DD + 8 * lc;
        #pragma unroll
        for (int it = 0; it < 4; it++) {
            const int r = lr + 16 * it;
            cpa16(swadr(Kd, r, lc), kp + (size_t)16 * it * KVHH * DD);
            cpa16(swadr(Vd, r, lc), vp + (size_t)16 * it * KVHH * DD);
        }
        asm volatile("cp.async.commit_group;");
    };

    // ---- prologue: issue tiles lo, lo+1; load+convert Q ----
    issue_tile(lo);
    if (lo + 1 <= hi) issue_tile(lo + 1);

    #pragma unroll
    for (int it = 0; it < 8; it++) {
        const int r = lr + 16 * it;
        const float* qp = q + ((size_t)((b * SS + q0 + r) * HH + h)) * DD + 8 * lc;
        float4 f0 = *(const float4*)qp;
        float4 f1 = *(const float4*)(qp + 4);
        uint4 u;
        u.x = pk(f0.x * qscale, f0.y * qscale);
        u.y = pk(f0.z * qscale, f0.w * qscale);
        u.z = pk(f1.x * qscale, f1.y * qscale);
        u.w = pk(f1.z * qscale, f1.w * qscale);
        asm volatile("st.shared.v4.b32 [%0], {%1,%2,%3,%4};"
                     :: "r"(swadr(Qb, r, lc)), "r"(u.x), "r"(u.y), "r"(u.z), "r"(u.w));
    }
    __syncthreads();

    // ---- Q fragments -> registers (held for whole kernel) ----
    uint32_t qf[8][4];
    #pragma unroll
    for (int i = 0; i < 8; i++)
        ldsm4(qf[i][0], qf[i][1], qf[i][2], qf[i][3], swadr(Qb, rowA, 2 * i + cA));

    float o[16][4];
    #pragma unroll
    for (int t = 0; t < 16; t++) { o[t][0] = 0.f; o[t][1] = 0.f; o[t][2] = 0.f; o[t][3] = 0.f; }
    float m0 = -1e30f, m1 = -1e30f, l0 = 0.f, l1 = 0.f;

    const int rlo = q0 + 16 * w, rhi = rlo + 15;
    const int ig0 = rlo + g, ig1 = ig0 + 8;

    for (int kt = lo; kt <= hi; kt++) {
        // wait for tile kt's group
        if (kt == hi) asm volatile("cp.async.wait_group 0;");
        else          asm volatile("cp.async.wait_group 1;");
        __syncthreads();   // tile kt visible to all; all warps done with tile kt-1

        if (kt + 2 <= hi) issue_tile(kt + 2);   // slot (kt+2)%3 == (kt-1)%3, now free

        const int j0 = kt * KTILE;
        const bool active = (j0 <= rhi) && (j0 + KTILE - 1 >= rlo - WIN + 1);
        if (active) {
            const uint32_t Kc = Rb + ((kt - lo) % 3) * 2 * KBYTES;
            const uint32_t Vc = Kc + KBYTES;
            const bool masked = (j0 + KTILE - 1 > rlo) || (rhi - j0 >= WIN);

            // ---- S = Q K^T ----
            float s[8][4];
            #pragma unroll
            for (int t = 0; t < 8; t++) { s[t][0] = 0.f; s[t][1] = 0.f; s[t][2] = 0.f; s[t][3] = 0.f; }
            #pragma unroll
            for (int i = 0; i < 8; i++) {
                #pragma unroll
                for (int p = 0; p < 4; p++) {
                    uint32_t b0, b1, b2, b3;
                    ldsm4(b0, b1, b2, b3, swadr(Kc, rowB + 16 * p, 2 * i + cB));
                    mma16(s[2 * p],     qf[i][0], qf[i][1], qf[i][2], qf[i][3], b0, b1);
                    mma16(s[2 * p + 1], qf[i][0], qf[i][1], qf[i][2], qf[i][3], b2, b3);
                }
            }

            // ---- softcap (+mask on edge tiles) + online softmax (no exp guards) ----
            float rmax0 = -1e30f, rmax1 = -1e30f;
            if (masked) {
                #pragma unroll
                for (int t = 0; t < 8; t++) {
                    const int jg = j0 + 8 * t + 2 * tg;
                    float v0 = 50.f * tanh_fast(s[t][0]);
                    float v1 = 50.f * tanh_fast(s[t][1]);
                    float v2 = 50.f * tanh_fast(s[t][2]);
                    float v3 = 50.f * tanh_fast(s[t][3]);
                    bool ok0 = (jg     <= ig0) && (ig0 - jg     < WIN);
                    bool ok1 = (jg + 1 <= ig0) && (ig0 - jg - 1 < WIN);
                    bool ok2 = (jg     <= ig1) && (ig1 - jg     < WIN);
                    bool ok3 = (jg + 1 <= ig1) && (ig1 - jg - 1 < WIN);
                    s[t][0] = ok0 ? v0 : -1e30f;
                    s[t][1] = ok1 ? v1 : -1e30f;
                    s[t][2] = ok2 ? v2 : -1e30f;
                    s[t][3] = ok3 ? v3 : -1e30f;
                    rmax0 = fmaxf(rmax0, fmaxf(s[t][0], s[t][1]));
                    rmax1 = fmaxf(rmax1, fmaxf(s[t][2], s[t][3]));
                }
            } else {
                #pragma unroll
                for (int t = 0; t < 8; t++) {
                    s[t][0] = 50.f * tanh_fast(s[t][0]);
                    s[t][1] = 50.f * tanh_fast(s[t][1]);
                    s[t][2] = 50.f * tanh_fast(s[t][2]);
                    s[t][3] = 50.f * tanh_fast(s[t][3]);
                    rmax0 = fmaxf(rmax0, fmaxf(s[t][0], s[t][1]));
                    rmax1 = fmaxf(rmax1, fmaxf(s[t][2], s[t][3]));
                }
            }
            rmax0 = fmaxf(rmax0, __shfl_xor_sync(0xffffffffu, rmax0, 1));
            rmax0 = fmaxf(rmax0, __shfl_xor_sync(0xffffffffu, rmax0, 2));
            rmax1 = fmaxf(rmax1, __shfl_xor_sync(0xffffffffu, rmax1, 1));
            rmax1 = fmaxf(rmax1, __shfl_xor_sync(0xffffffffu, rmax1, 2));

            const float m0n = fmaxf(m0, rmax0);
            const float m1n = fmaxf(m1, rmax1);
            const float al0 = ex2((m0 - m0n) * LOG2E);
            const float al1 = ex2((m1 - m1n) * LOG2E);
            m0 = m0n; m1 = m1n;

            float ls0 = 0.f, ls1 = 0.f;
            #pragma unroll
            for (int t = 0; t < 8; t++) {
                // masked entries: s = -1e30 -> exponent ~ -1e30 -> ex2 underflows to 0.
                // all-masked-row case (m = -1e30) self-heals: alpha=0 at first real tile.
                float p0 = ex2((s[t][0] - m0n) * LOG2E);
                float p1 = ex2((s[t][1] - m0n) * LOG2E);
                float p2 = ex2((s[t][2] - m1n) * LOG2E);
                float p3 = ex2((s[t][3] - m1n) * LOG2E);
                s[t][0] = p0; s[t][1] = p1; s[t][2] = p2; s[t][3] = p3;
                ls0 += p0 + p1; ls1 += p2 + p3;
            }
            ls0 += __shfl_xor_sync(0xffffffffu, ls0, 1);
            ls0 += __shfl_xor_sync(0xffffffffu, ls0, 2);
            ls1 += __shfl_xor_sync(0xffffffffu, ls1, 1);
            ls1 += __shfl_xor_sync(0xffffffffu, ls1, 2);
            l0 = l0 * al0 + ls0;
            l1 = l1 * al1 + ls1;

            #pragma unroll
            for (int t = 0; t < 16; t++) {
                o[t][0] *= al0; o[t][1] *= al0; o[t][2] *= al1; o[t][3] *= al1;
            }

            // ---- PV ----
            #pragma unroll
            for (int u = 0; u < 4; u++) {
                const uint32_t a0 = pk(s[2*u][0],   s[2*u][1]);
                const uint32_t a1 = pk(s[2*u][2],   s[2*u][3]);
                const uint32_t a2 = pk(s[2*u+1][0], s[2*u+1][1]);
                const uint32_t a3 = pk(s[2*u+1][2], s[2*u+1][3]);
                #pragma unroll
                for (int p = 0; p < 8; p++) {
                    uint32_t b0, b1, b2, b3;
                    ldsm4t(b0, b1, b2, b3, swadr(Vc, 16 * u + rowV_, 2 * p + cV));
                    mma16(o[2 * p],     a0, a1, a2, a3, b0, b1);
                    mma16(o[2 * p + 1], a0, a1, a2, a3, b2, b3);
                }
            }
        }
    }

    // ---- write output ----
    const float inv0 = 1.f / l0;
    const float inv1 = 1.f / l1;
    const size_t base0 = ((size_t)((b * SS + ig0) * HH + h)) * DD;
    const size_t base1 = ((size_t)((b * SS + ig1) * HH + h)) * DD;
    #pragma unroll
    for (int t = 0; t < 16; t++) {
        const int col = 8 * t + 2 * tg;
        *(float2*)&out[base0 + col] = make_float2(o[t][0] * inv0, o[t][1] * inv0);
        *(float2*)&out[base1 + col] = make_float2(o[t][2] * inv1, o[t][3] * inv1);
    }
}

extern "C" void kernel_launch(void* const* d_in, const int* in_sizes, int n_in,
                              void* d_out, int out_size)
{
    const float* q = (const float*)d_in[0];   // query  [4096,32,128]
    const float* k = (const float*)d_in[1];   // key    [4096, 8,128]
    const float* v = (const float*)d_in[2];   // value  [4096, 8,128]
    // d_in[3..5] (caches + block table) do not affect the output: the cache
    // write-then-gather of the same permutation blocks returns key/value unchanged.
    float* out = (float*)d_out;

    convert_kv<<<KV_ELEMS / (256 * 8), 256>>>(k, v);

    cudaFuncSetAttribute(attn_kernel,
                         cudaFuncAttributeMaxDynamicSharedMemorySize,
                         SMEM_BYTES);
    dim3 grid(SS / QTILE, HH, BB);   // 8 x 32 x 4 = 1024 blocks
    attn_kernel<<<grid, NT, SMEM_BYTES>>>(q, out);
}

// round 9
// speedup vs baseline: 1.9973x; 1.0257x over previous
#include <cuda_runtime.h>
#include <cuda_fp16.h>
#include <stdint.h>

#define BB 4
#define SS 1024
#define HH 32
#define KVHH 8
#define DD 128
#define QTILE 128
#define KTILE 64
#define WIN 512
#define NT 256

#define KV_ELEMS (BB * SS * KVHH * DD)   // 4194304

// fp16 K/V scratch (pre-converted by convert_kv kernel)
__device__ __half KH[KV_ELEMS];
__device__ __half VH[KV_ELEMS];

// smem: Q 128x256B = 32KB, ring of 3 x (K 16KB + V 16KB) = 96KB -> 128KB
#define QBYTES (128 * 256)
#define KBYTES (64 * 256)
#define SMEM_BYTES (QBYTES + 6 * KBYTES)

__device__ __forceinline__ uint32_t swadr(uint32_t base, int row, int chunk) {
    return base + row * 256 + ((chunk ^ (row & 7)) << 4);
}
__device__ __forceinline__ float tanh_fast(float x) {
    float y; asm("tanh.approx.f32 %0, %1;" : "=f"(y) : "f"(x)); return y;
}
__device__ __forceinline__ float ex2(float x) {
    float y; asm("ex2.approx.f32 %0, %1;" : "=f"(y) : "f"(x)); return y;
}
__device__ __forceinline__ uint32_t ex2h2(uint32_t a) {
    uint32_t d; asm("ex2.approx.f16x2 %0, %1;" : "=r"(d) : "r"(a)); return d;
}
__device__ __forceinline__ uint32_t pk(float lo, float hi) {
    __half2 h = __floats2half2_rn(lo, hi);
    return *(uint32_t*)&h;
}
__device__ __forceinline__ void ldsm4(uint32_t& r0, uint32_t& r1, uint32_t& r2, uint32_t& r3, uint32_t a) {
    asm volatile("ldmatrix.sync.aligned.m8n8.x4.shared.b16 {%0,%1,%2,%3},[%4];"
                 : "=r"(r0), "=r"(r1), "=r"(r2), "=r"(r3) : "r"(a));
}
__device__ __forceinline__ void ldsm4t(uint32_t& r0, uint32_t& r1, uint32_t& r2, uint32_t& r3, uint32_t a) {
    asm volatile("ldmatrix.sync.aligned.m8n8.x4.trans.shared.b16 {%0,%1,%2,%3},[%4];"
                 : "=r"(r0), "=r"(r1), "=r"(r2), "=r"(r3) : "r"(a));
}
__device__ __forceinline__ void mma16(float* d, uint32_t a0, uint32_t a1, uint32_t a2, uint32_t a3,
                                      uint32_t b0, uint32_t b1) {
    asm volatile(
        "mma.sync.aligned.m16n8k16.row.col.f32.f16.f16.f32 "
        "{%0,%1,%2,%3}, {%4,%5,%6,%7}, {%8,%9}, {%0,%1,%2,%3};"
        : "+f"(d[0]), "+f"(d[1]), "+f"(d[2]), "+f"(d[3])
        : "r"(a0), "r"(a1), "r"(a2), "r"(a3), "r"(b0), "r"(b1));
}
__device__ __forceinline__ void cpa16(uint32_t dst, const __half* src) {
    asm volatile("cp.async.cg.shared.global [%0], [%1], 16;" :: "r"(dst), "l"(src));
}

// ---- pre-pass: fp32 -> fp16 (round-to-nearest) for K and V ----
__global__ __launch_bounds__(256, 8)
void convert_kv(const float* __restrict__ k, const float* __restrict__ v) {
    const int i = (blockIdx.x * 256 + threadIdx.x) * 8;
    float4 a = *(const float4*)&k[i];
    float4 b = *(const float4*)&k[i + 4];
    uint4 u;
    u.x = pk(a.x, a.y); u.y = pk(a.z, a.w); u.z = pk(b.x, b.y); u.w = pk(b.z, b.w);
    *(uint4*)&KH[i] = u;
    a = *(const float4*)&v[i];
    b = *(const float4*)&v[i + 4];
    u.x = pk(a.x, a.y); u.y = pk(a.z, a.w); u.z = pk(b.x, b.y); u.w = pk(b.z, b.w);
    *(uint4*)&VH[i] = u;
}

__global__ __launch_bounds__(NT, 1)
void attn_kernel(const float* __restrict__ q, float* __restrict__ out)
{
    extern __shared__ char smraw[];
    uint32_t smb;
    asm("{ .reg .u64 t; cvta.to.shared.u64 t, %1; cvt.u32.u64 %0, t; }" : "=r"(smb) : "l"(smraw));
    const uint32_t Qb = smb, Rb = smb + QBYTES;   // ring base

    const int qt = blockIdx.x, h = blockIdx.y, b = blockIdx.z;
    const int kvh = h >> 2;
    const int q0  = qt * QTILE;
    const int tid = threadIdx.x, lane = tid & 31, w = tid >> 5;
    const int g = lane >> 2, tg = lane & 3;

    const int lr = tid >> 4;   // 0..15
    const int lc = tid & 15;   // chunk 0..15

    const int rowA  = 16 * w + (lane & 7) + 8 * ((lane >> 3) & 1);
    const int cA    = lane >> 4;
    const int rowB  = (lane & 7) + 8 * (lane >> 4);
    const int cB    = (lane >> 3) & 1;
    const int rowV_ = (lane & 7) + 8 * ((lane >> 3) & 1);
    const int cV    = lane >> 4;

    const int lo = (q0 - WIN + 1 > 0) ? ((q0 - WIN + 1) >> 6) : 0;
    const int hi = (q0 + QTILE - 1) >> 6;

    const float qscale = 0.08838834764831843f * 0.02f;   // (1/sqrt(128)) / 50
    const float LOG2E  = 1.4426950408889634f;
    const uint32_t ONE2 = 0x3C003C00u;                   // h2(1,1)

    // issue cp.async for tile kt into ring slot (kt-lo)%3
    auto issue_tile = [&](int kt) {
        const int j0 = kt * KTILE;
        const uint32_t Kd = Rb + ((kt - lo) % 3) * 2 * KBYTES;
        const uint32_t Vd = Kd + KBYTES;
        const __half* kp = KH + ((size_t)((b * SS + j0 + lr) * KVHH + kvh)) * DD + 8 * lc;
        const __half* vp = VH + ((size_t)((b * SS + j0 + lr) * KVHH + kvh)) * DD + 8 * lc;
        #pragma unroll
        for (int it = 0; it < 4; it++) {
            const int r = lr + 16 * it;
            cpa16(swadr(Kd, r, lc), kp + (size_t)16 * it * KVHH * DD);
            cpa16(swadr(Vd, r, lc), vp + (size_t)16 * it * KVHH * DD);
        }
        asm volatile("cp.async.commit_group;");
    };

    // ---- prologue: issue tiles lo, lo+1; load+convert Q ----
    issue_tile(lo);
    if (lo + 1 <= hi) issue_tile(lo + 1);

    #pragma unroll
    for (int it = 0; it < 8; it++) {
        const int r = lr + 16 * it;
        const float* qp = q + ((size_t)((b * SS + q0 + r) * HH + h)) * DD + 8 * lc;
        float4 f0 = *(const float4*)qp;
        float4 f1 = *(const float4*)(qp + 4);
        uint4 u;
        u.x = pk(f0.x * qscale, f0.y * qscale);
        u.y = pk(f0.z * qscale, f0.w * qscale);
        u.z = pk(f1.x * qscale, f1.y * qscale);
        u.w = pk(f1.z * qscale, f1.w * qscale);
        asm volatile("st.shared.v4.b32 [%0], {%1,%2,%3,%4};"
                     :: "r"(swadr(Qb, r, lc)), "r"(u.x), "r"(u.y), "r"(u.z), "r"(u.w));
    }
    __syncthreads();

    // ---- Q fragments -> registers (held for whole kernel) ----
    uint32_t qf[8][4];
    #pragma unroll
    for (int i = 0; i < 8; i++)
        ldsm4(qf[i][0], qf[i][1], qf[i][2], qf[i][3], swadr(Qb, rowA, 2 * i + cA));

    float o[16][4];
    #pragma unroll
    for (int t = 0; t < 16; t++) { o[t][0] = 0.f; o[t][1] = 0.f; o[t][2] = 0.f; o[t][3] = 0.f; }
    float accl[4] = {0.f, 0.f, 0.f, 0.f};   // l via ones-column MMA
    // m init: scores are in [-50, 50] after softcap, so -51 is a strict lower
    // bound for any REAL score -> m stays finite forever; fully-masked rows
    // produce P=0 (s=-1e30 -> fp16 -inf -> ex2 -> +0), no degenerate cases.
    float m0 = -51.f, m1 = -51.f;

    const int rlo = q0 + 16 * w, rhi = rlo + 15;
    const int ig0 = rlo + g, ig1 = ig0 + 8;

    for (int kt = lo; kt <= hi; kt++) {
        // wait for tile kt's group
        if (kt == hi) asm volatile("cp.async.wait_group 0;");
        else          asm volatile("cp.async.wait_group 1;");
        __syncthreads();   // tile kt visible to all; all warps done with tile kt-1

        if (kt + 2 <= hi) issue_tile(kt + 2);   // slot (kt+2)%3 == (kt-1)%3, now free

        const int j0 = kt * KTILE;
        const bool active = (j0 <= rhi) && (j0 + KTILE - 1 >= rlo - WIN + 1);
        if (active) {
            const uint32_t Kc = Rb + ((kt - lo) % 3) * 2 * KBYTES;
            const uint32_t Vc = Kc + KBYTES;
            const bool masked = (j0 + KTILE - 1 > rlo) || (rhi - j0 >= WIN);

            // ---- S = Q K^T ----
            float s[8][4];
            #pragma unroll
            for (int t = 0; t < 8; t++) { s[t][0] = 0.f; s[t][1] = 0.f; s[t][2] = 0.f; s[t][3] = 0.f; }
            #pragma unroll
            for (int i = 0; i < 8; i++) {
                #pragma unroll
                for (int p = 0; p < 4; p++) {
                    uint32_t b0, b1, b2, b3;
                    ldsm4(b0, b1, b2, b3, swadr(Kc, rowB + 16 * p, 2 * i + cB));
                    mma16(s[2 * p],     qf[i][0], qf[i][1], qf[i][2], qf[i][3], b0, b1);
                    mma16(s[2 * p + 1], qf[i][0], qf[i][1], qf[i][2], qf[i][3], b2, b3);
                }
            }

            // ---- softcap (+mask on edge tiles) + row max ----
            float rmax0 = -1e30f, rmax1 = -1e30f;
            if (masked) {
                #pragma unroll
                for (int t = 0; t < 8; t++) {
                    const int jg = j0 + 8 * t + 2 * tg;
                    float v0 = 50.f * tanh_fast(s[t][0]);
                    float v1 = 50.f * tanh_fast(s[t][1]);
                    float v2 = 50.f * tanh_fast(s[t][2]);
                    float v3 = 50.f * tanh_fast(s[t][3]);
                    bool ok0 = (jg     <= ig0) && (ig0 - jg     < WIN);
                    bool ok1 = (jg + 1 <= ig0) && (ig0 - jg - 1 < WIN);
                    bool ok2 = (jg     <= ig1) && (ig1 - jg     < WIN);
                    bool ok3 = (jg + 1 <= ig1) && (ig1 - jg - 1 < WIN);
                    s[t][0] = ok0 ? v0 : -1e30f;
                    s[t][1] = ok1 ? v1 : -1e30f;
                    s[t][2] = ok2 ? v2 : -1e30f;
                    s[t][3] = ok3 ? v3 : -1e30f;
                    rmax0 = fmaxf(rmax0, fmaxf(s[t][0], s[t][1]));
                    rmax1 = fmaxf(rmax1, fmaxf(s[t][2], s[t][3]));
                }
            } else {
                #pragma unroll
                for (int t = 0; t < 8; t++) {
                    s[t][0] = 50.f * tanh_fast(s[t][0]);
                    s[t][1] = 50.f * tanh_fast(s[t][1]);
                    s[t][2] = 50.f * tanh_fast(s[t][2]);
                    s[t][3] = 50.f * tanh_fast(s[t][3]);
                    rmax0 = fmaxf(rmax0, fmaxf(s[t][0], s[t][1]));
                    rmax1 = fmaxf(rmax1, fmaxf(s[t][2], s[t][3]));
                }
            }
            rmax0 = fmaxf(rmax0, __shfl_xor_sync(0xffffffffu, rmax0, 1));
            rmax0 = fmaxf(rmax0, __shfl_xor_sync(0xffffffffu, rmax0, 2));
            rmax1 = fmaxf(rmax1, __shfl_xor_sync(0xffffffffu, rmax1, 1));
            rmax1 = fmaxf(rmax1, __shfl_xor_sync(0xffffffffu, rmax1, 2));

            // m stays finite: rmax may be -1e30 (fully masked row) but m >= -51 always
            const float m0n = fmaxf(m0, rmax0);
            const float m1n = fmaxf(m1, rmax1);
            const float al0 = ex2((m0 - m0n) * LOG2E);   // args in [-101*LOG2E, 0]
            const float al1 = ex2((m1 - m1n) * LOG2E);
            m0 = m0n; m1 = m1n;
            const float mL0 = m0n * LOG2E, mL1 = m1n * LOG2E;

            // ---- P = exp2 directly in f16x2 (these ARE the mma A-fragments) ----
            // masked s=-1e30: arg ~ -1.44e30 -> fp16 -inf -> ex2 -> +0 (exact)
            uint32_t pf[16];
            #pragma unroll
            for (int u = 0; u < 4; u++) {
                pf[4*u+0] = ex2h2(pk(s[2*u][0]   * LOG2E - mL0, s[2*u][1]   * LOG2E - mL0));
                pf[4*u+1] = ex2h2(pk(s[2*u][2]   * LOG2E - mL1, s[2*u][3]   * LOG2E - mL1));
                pf[4*u+2] = ex2h2(pk(s[2*u+1][0] * LOG2E - mL0, s[2*u+1][1] * LOG2E - mL0));
                pf[4*u+3] = ex2h2(pk(s[2*u+1][2] * LOG2E - mL1, s[2*u+1][3] * LOG2E - mL1));
            }

            // ---- rescale O and l-accumulator ----
            #pragma unroll
            for (int t = 0; t < 16; t++) {
                o[t][0] *= al0; o[t][1] *= al0; o[t][2] *= al1; o[t][3] *= al1;
            }
            accl[0] *= al0; accl[1] *= al0; accl[2] *= al1; accl[3] *= al1;

            // ---- PV (+ ones-column MMA accumulates row sums into accl) ----
            #pragma unroll
            for (int u = 0; u < 4; u++) {
                const uint32_t a0 = pf[4*u+0], a1 = pf[4*u+1], a2 = pf[4*u+2], a3 = pf[4*u+3];
                mma16(accl, a0, a1, a2, a3, ONE2, ONE2);
                #pragma unroll
                for (int p = 0; p < 8; p++) {
                    uint32_t b0, b1, b2, b3;
                    ldsm4t(b0, b1, b2, b3, swadr(Vc, 16 * u + rowV_, 2 * p + cV));
                    mma16(o[2 * p],     a0, a1, a2, a3, b0, b1);
                    mma16(o[2 * p + 1], a0, a1, a2, a3, b2, b3);
                }
            }
        }
    }

    // ---- write output (accl[0] = l for row ig0, accl[2] = l for row ig1) ----
    const float inv0 = 1.f / accl[0];
    const float inv1 = 1.f / accl[2];
    const size_t base0 = ((size_t)((b * SS + ig0) * HH + h)) * DD;
    const size_t base1 = ((size_t)((b * SS + ig1) * HH + h)) * DD;
    #pragma unroll
    for (int t = 0; t < 16; t++) {
        const int col = 8 * t + 2 * tg;
        *(float2*)&out[base0 + col] = make_float2(o[t][0] * inv0, o[t][1] * inv0);
        *(float2*)&out[base1 + col] = make_float2(o[t][2] * inv1, o[t][3] * inv1);
    }
}

extern "C" void kernel_launch(void* const* d_in, const int* in_sizes, int n_in,
                              void* d_out, int out_size)
{
    const float* q = (const float*)d_in[0];   // query  [4096,32,128]
    const float* k = (const float*)d_in[1];   // key    [4096, 8,128]
    const float* v = (const float*)d_in[2];   // value  [4096, 8,128]
    // d_in[3..5] (caches + block table) do not affect the output: the cache
    // write-then-gather of the same permutation blocks returns key/value unchanged.
    float* out = (float*)d_out;

    convert_kv<<<KV_ELEMS / (256 * 8), 256>>>(k, v);

    cudaFuncSetAttribute(attn_kernel,
                         cudaFuncAttributeMaxDynamicSharedMemorySize,
                         SMEM_BYTES);
    dim3 grid(SS / QTILE, HH, BB);   // 8 x 32 x 4 = 1024 blocks
    attn_kernel<<<grid, NT, SMEM_BYTES>>>(q, out);
}

// round 10
// speedup vs baseline: 2.0968x; 1.0498x over previous
#include <cuda_runtime.h>
#include <cuda_fp16.h>
#include <stdint.h>

#define BB 4
#define SS 1024
#define HH 32
#define KVHH 8
#define DD 128
#define QTILE 128
#define KTILE 64
#define WIN 512
#define NT 256
#define NSLOT 4

#define KV_ELEMS (BB * SS * KVHH * DD)   // 4194304

// fp16 K/V scratch (pre-converted by convert_kv kernel)
__device__ __half KH[KV_ELEMS];
__device__ __half VH[KV_ELEMS];

// smem: Q 32KB + ring 4 x (K 16KB + V 16KB) = 128KB + barriers
#define QBYTES (128 * 256)
#define KBYTES (64 * 256)
#define BAR_OFF (QBYTES + NSLOT * 2 * KBYTES)   // 163840
#define SMEM_BYTES (BAR_OFF + NSLOT * 16)

__device__ __forceinline__ uint32_t swadr(uint32_t base, int row, int chunk) {
    return base + row * 256 + ((chunk ^ (row & 7)) << 4);
}
__device__ __forceinline__ float tanh_fast(float x) {
    float y; asm("tanh.approx.f32 %0, %1;" : "=f"(y) : "f"(x)); return y;
}
__device__ __forceinline__ float ex2(float x) {
    float y; asm("ex2.approx.f32 %0, %1;" : "=f"(y) : "f"(x)); return y;
}
__device__ __forceinline__ uint32_t ex2h2(uint32_t a) {
    uint32_t d; asm("ex2.approx.f16x2 %0, %1;" : "=r"(d) : "r"(a)); return d;
}
__device__ __forceinline__ uint32_t pk(float lo, float hi) {
    __half2 h = __floats2half2_rn(lo, hi);
    return *(uint32_t*)&h;
}
__device__ __forceinline__ void ldsm4(uint32_t& r0, uint32_t& r1, uint32_t& r2, uint32_t& r3, uint32_t a) {
    asm volatile("ldmatrix.sync.aligned.m8n8.x4.shared.b16 {%0,%1,%2,%3},[%4];"
                 : "=r"(r0), "=r"(r1), "=r"(r2), "=r"(r3) : "r"(a));
}
__device__ __forceinline__ void ldsm4t(uint32_t& r0, uint32_t& r1, uint32_t& r2, uint32_t& r3, uint32_t a) {
    asm volatile("ldmatrix.sync.aligned.m8n8.x4.trans.shared.b16 {%0,%1,%2,%3},[%4];"
                 : "=r"(r0), "=r"(r1), "=r"(r2), "=r"(r3) : "r"(a));
}
__device__ __forceinline__ void mma16(float* d, uint32_t a0, uint32_t a1, uint32_t a2, uint32_t a3,
                                      uint32_t b0, uint32_t b1) {
    asm volatile(
        "mma.sync.aligned.m16n8k16.row.col.f32.f16.f16.f32 "
        "{%0,%1,%2,%3}, {%4,%5,%6,%7}, {%8,%9}, {%0,%1,%2,%3};"
        : "+f"(d[0]), "+f"(d[1]), "+f"(d[2]), "+f"(d[3])
        : "r"(a0), "r"(a1), "r"(a2), "r"(a3), "r"(b0), "r"(b1));
}
__device__ __forceinline__ void cpa16(uint32_t dst, const __half* src) {
    asm volatile("cp.async.cg.shared.global [%0], [%1], 16;" :: "r"(dst), "l"(src));
}
__device__ __forceinline__ void mbar_init(uint32_t a, uint32_t cnt) {
    asm volatile("mbarrier.init.shared.b64 [%0], %1;" :: "r"(a), "r"(cnt) : "memory");
}
__device__ __forceinline__ void mbar_arrive(uint32_t a) {
    asm volatile("mbarrier.arrive.release.cta.shared::cta.b64 _, [%0];" :: "r"(a) : "memory");
}
__device__ __forceinline__ void cpa_arrive(uint32_t a) {
    asm volatile("cp.async.mbarrier.arrive.noinc.shared::cta.b64 [%0];" :: "r"(a) : "memory");
}
__device__ __forceinline__ void mbar_wait(uint32_t a, uint32_t parity) {
    asm volatile(
        "{\n\t.reg .pred P1;\n\t"
        "WAIT_LOOP_%=:\n\t"
        "mbarrier.try_wait.parity.acquire.cta.shared::cta.b64 P1, [%0], %1, 0x989680;\n\t"
        "@P1 bra.uni WAIT_DONE_%=;\n\t"
        "bra.uni WAIT_LOOP_%=;\n\t"
        "WAIT_DONE_%=:\n\t}"
        :: "r"(a), "r"(parity) : "memory");
}

// ---- pre-pass: fp32 -> fp16 (round-to-nearest) for K and V ----
__global__ __launch_bounds__(256, 8)
void convert_kv(const float* __restrict__ k, const float* __restrict__ v) {
    const int i = (blockIdx.x * 256 + threadIdx.x) * 8;
    float4 a = *(const float4*)&k[i];
    float4 b = *(const float4*)&k[i + 4];
    uint4 u;
    u.x = pk(a.x, a.y); u.y = pk(a.z, a.w); u.z = pk(b.x, b.y); u.w = pk(b.z, b.w);
    *(uint4*)&KH[i] = u;
    a = *(const float4*)&v[i];
    b = *(const float4*)&v[i + 4];
    u.x = pk(a.x, a.y); u.y = pk(a.z, a.w); u.z = pk(b.x, b.y); u.w = pk(b.z, b.w);
    *(uint4*)&VH[i] = u;
}

__global__ __launch_bounds__(NT, 1)
void attn_kernel(const float* __restrict__ q, float* __restrict__ out)
{
    extern __shared__ char smraw[];
    uint32_t smb;
    asm("{ .reg .u64 t; cvta.to.shared.u64 t, %1; cvt.u32.u64 %0, t; }" : "=r"(smb) : "l"(smraw));
    const uint32_t Qb = smb, Rb = smb + QBYTES, Bar = smb + BAR_OFF;
    // full[s] = Bar + 16s ; empty[s] = Bar + 16s + 8

    const int qt = blockIdx.x, h = blockIdx.y, b = blockIdx.z;
    const int kvh = h >> 2;
    const int q0  = qt * QTILE;
    const int tid = threadIdx.x, lane = tid & 31, w = tid >> 5;
    const int g = lane >> 2, tg = lane & 3;

    const int lr = tid >> 4;   // 0..15
    const int lc = tid & 15;   // chunk 0..15

    const int rowA  = 16 * w + (lane & 7) + 8 * ((lane >> 3) & 1);
    const int cA    = lane >> 4;
    const int rowB  = (lane & 7) + 8 * (lane >> 4);
    const int cB    = (lane >> 3) & 1;
    const int rowV_ = (lane & 7) + 8 * ((lane >> 3) & 1);
    const int cV    = lane >> 4;

    const int lo = (q0 - WIN + 1 > 0) ? ((q0 - WIN + 1) >> 6) : 0;
    const int hi = (q0 + QTILE - 1) >> 6;

    const float qscale = 0.08838834764831843f * 0.02f;   // (1/sqrt(128)) / 50
    const float LOG2E  = 1.4426950408889634f;
    const uint32_t ONE2 = 0x3C003C00u;                   // h2(1,1)

    // ---- init mbarriers before any cp.async targets them ----
    if (tid == 0) {
        #pragma unroll
        for (int s = 0; s < NSLOT; s++) {
            mbar_init(Bar + 16 * s,     NT);   // full: 256 async-group arrivals
            mbar_init(Bar + 16 * s + 8, NT);   // empty: 256 thread arrivals
        }
    }
    __syncthreads();

    // issue this thread's cp.async portion of tile t into slot (t-lo)&3
    auto issue_tile = [&](int t) {
        const int slot = (t - lo) & (NSLOT - 1);
        const int j0 = t * KTILE;
        const uint32_t Kd = Rb + slot * 2 * KBYTES;
        const uint32_t Vd = Kd + KBYTES;
        const __half* kp = KH + ((size_t)((b * SS + j0 + lr) * KVHH + kvh)) * DD + 8 * lc;
        const __half* vp = VH + ((size_t)((b * SS + j0 + lr) * KVHH + kvh)) * DD + 8 * lc;
        #pragma unroll
        for (int it = 0; it < 4; it++) {
            const int r = lr + 16 * it;
            cpa16(swadr(Kd, r, lc), kp + (size_t)16 * it * KVHH * DD);
            cpa16(swadr(Vd, r, lc), vp + (size_t)16 * it * KVHH * DD);
        }
        cpa_arrive(Bar + 16 * slot);   // arrive on full[slot] when this thread's copies land
    };

    // ---- prologue: issue up to 3 tiles ----
    issue_tile(lo);
    if (lo + 1 <= hi) issue_tile(lo + 1);
    if (lo + 2 <= hi) issue_tile(lo + 2);

    // ---- Q: LDG -> scale -> fp16 -> swizzled STS ----
    #pragma unroll
    for (int it = 0; it < 8; it++) {
        const int r = lr + 16 * it;
        const float* qp = q + ((size_t)((b * SS + q0 + r) * HH + h)) * DD + 8 * lc;
        float4 f0 = *(const float4*)qp;
        float4 f1 = *(const float4*)(qp + 4);
        uint4 u;
        u.x = pk(f0.x * qscale, f0.y * qscale);
        u.y = pk(f0.z * qscale, f0.w * qscale);
        u.z = pk(f1.x * qscale, f1.y * qscale);
        u.w = pk(f1.z * qscale, f1.w * qscale);
        asm volatile("st.shared.v4.b32 [%0], {%1,%2,%3,%4};"
                     :: "r"(swadr(Qb, r, lc)), "r"(u.x), "r"(u.y), "r"(u.z), "r"(u.w));
    }
    __syncthreads();   // Q tile visible to all warps (cross-warp row ownership)

    // ---- Q fragments -> registers (held for whole kernel) ----
    uint32_t qf[8][4];
    #pragma unroll
    for (int i = 0; i < 8; i++)
        ldsm4(qf[i][0], qf[i][1], qf[i][2], qf[i][3], swadr(Qb, rowA, 2 * i + cA));

    float o[16][4];
    #pragma unroll
    for (int t = 0; t < 16; t++) { o[t][0] = 0.f; o[t][1] = 0.f; o[t][2] = 0.f; o[t][3] = 0.f; }
    float accl[4] = {0.f, 0.f, 0.f, 0.f};   // l via ones-column MMA
    // m init -51: strict lower bound of any real (softcapped) score; m stays
    // finite always, masked rows yield P=0 via fp16 -inf -> ex2 -> +0.
    float m0 = -51.f, m1 = -51.f;

    const int rlo = q0 + 16 * w, rhi = rlo + 15;
    const int ig0 = rlo + g, ig1 = ig0 + 8;

    for (int kt = lo; kt <= hi; kt++) {
        const int ti = kt - lo;

        // issue tile kt+3 once slot (ti+3)&3 is drained by all threads
        if (kt + 3 <= hi) {
            const int xi = ti + 3;
            const int slot3 = xi & (NSLOT - 1);
            if (xi >= NSLOT) mbar_wait(Bar + 16 * slot3 + 8, ((xi >> 2) - 1) & 1);
            issue_tile(kt + 3);
        }

        const int slot = ti & (NSLOT - 1);
        mbar_wait(Bar + 16 * slot, (ti >> 2) & 1);   // tile kt data ready (acquire)

        const int j0 = kt * KTILE;
        const bool active = (j0 <= rhi) && (j0 + KTILE - 1 >= rlo - WIN + 1);
        if (active) {
            const uint32_t Kc = Rb + slot * 2 * KBYTES;
            const uint32_t Vc = Kc + KBYTES;
            const bool masked = (j0 + KTILE - 1 > rlo) || (rhi - j0 >= WIN);

            // ---- S = Q K^T ----
            float s[8][4];
            #pragma unroll
            for (int t = 0; t < 8; t++) { s[t][0] = 0.f; s[t][1] = 0.f; s[t][2] = 0.f; s[t][3] = 0.f; }
            #pragma unroll
            for (int i = 0; i < 8; i++) {
                #pragma unroll
                for (int p = 0; p < 4; p++) {
                    uint32_t b0, b1, b2, b3;
                    ldsm4(b0, b1, b2, b3, swadr(Kc, rowB + 16 * p, 2 * i + cB));
                    mma16(s[2 * p],     qf[i][0], qf[i][1], qf[i][2], qf[i][3], b0, b1);
                    mma16(s[2 * p + 1], qf[i][0], qf[i][1], qf[i][2], qf[i][3], b2, b3);
                }
            }

            // ---- softcap (+mask on edge tiles) + row max ----
            float rmax0 = -1e30f, rmax1 = -1e30f;
            if (masked) {
                #pragma unroll
                for (int t = 0; t < 8; t++) {
                    const int jg = j0 + 8 * t + 2 * tg;
                    float v0 = 50.f * tanh_fast(s[t][0]);
                    float v1 = 50.f * tanh_fast(s[t][1]);
                    float v2 = 50.f * tanh_fast(s[t][2]);
                    float v3 = 50.f * tanh_fast(s[t][3]);
                    bool ok0 = (jg     <= ig0) && (ig0 - jg     < WIN);
                    bool ok1 = (jg + 1 <= ig0) && (ig0 - jg - 1 < WIN);
                    bool ok2 = (jg     <= ig1) && (ig1 - jg     < WIN);
                    bool ok3 = (jg + 1 <= ig1) && (ig1 - jg - 1 < WIN);
                    s[t][0] = ok0 ? v0 : -1e30f;
                    s[t][1] = ok1 ? v1 : -1e30f;
                    s[t][2] = ok2 ? v2 : -1e30f;
                    s[t][3] = ok3 ? v3 : -1e30f;
                    rmax0 = fmaxf(rmax0, fmaxf(s[t][0], s[t][1]));
                    rmax1 = fmaxf(rmax1, fmaxf(s[t][2], s[t][3]));
                }
            } else {
                #pragma unroll
                for (int t = 0; t < 8; t++) {
                    s[t][0] = 50.f * tanh_fast(s[t][0]);
                    s[t][1] = 50.f * tanh_fast(s[t][1]);
                    s[t][2] = 50.f * tanh_fast(s[t][2]);
                    s[t][3] = 50.f * tanh_fast(s[t][3]);
                    rmax0 = fmaxf(rmax0, fmaxf(s[t][0], s[t][1]));
                    rmax1 = fmaxf(rmax1, fmaxf(s[t][2], s[t][3]));
                }
            }
            rmax0 = fmaxf(rmax0, __shfl_xor_sync(0xffffffffu, rmax0, 1));
            rmax0 = fmaxf(rmax0, __shfl_xor_sync(0xffffffffu, rmax0, 2));
            rmax1 = fmaxf(rmax1, __shfl_xor_sync(0xffffffffu, rmax1, 1));
            rmax1 = fmaxf(rmax1, __shfl_xor_sync(0xffffffffu, rmax1, 2));

            const float m0n = fmaxf(m0, rmax0);
            const float m1n = fmaxf(m1, rmax1);
            const float al0 = ex2((m0 - m0n) * LOG2E);
            const float al1 = ex2((m1 - m1n) * LOG2E);
            m0 = m0n; m1 = m1n;
            const float mL0 = m0n * LOG2E, mL1 = m1n * LOG2E;

            // ---- P = exp2 directly in f16x2 (these ARE the mma A-fragments) ----
            uint32_t pf[16];
            #pragma unroll
            for (int u = 0; u < 4; u++) {
                pf[4*u+0] = ex2h2(pk(s[2*u][0]   * LOG2E - mL0, s[2*u][1]   * LOG2E - mL0));
                pf[4*u+1] = ex2h2(pk(s[2*u][2]   * LOG2E - mL1, s[2*u][3]   * LOG2E - mL1));
                pf[4*u+2] = ex2h2(pk(s[2*u+1][0] * LOG2E - mL0, s[2*u+1][1] * LOG2E - mL0));
                pf[4*u+3] = ex2h2(pk(s[2*u+1][2] * LOG2E - mL1, s[2*u+1][3] * LOG2E - mL1));
            }

            // ---- rescale O and l-accumulator ----
            #pragma unroll
            for (int t = 0; t < 16; t++) {
                o[t][0] *= al0; o[t][1] *= al0; o[t][2] *= al1; o[t][3] *= al1;
            }
            accl[0] *= al0; accl[1] *= al0; accl[2] *= al1; accl[3] *= al1;

            // ---- PV (+ ones-column MMA accumulates row sums into accl) ----
            #pragma unroll
            for (int u = 0; u < 4; u++) {
                const uint32_t a0 = pf[4*u+0], a1 = pf[4*u+1], a2 = pf[4*u+2], a3 = pf[4*u+3];
                mma16(accl, a0, a1, a2, a3, ONE2, ONE2);
                #pragma unroll
                for (int p = 0; p < 8; p++) {
                    uint32_t b0, b1, b2, b3;
                    ldsm4t(b0, b1, b2, b3, swadr(Vc, 16 * u + rowV_, 2 * p + cV));
                    mma16(o[2 * p],     a0, a1, a2, a3, b0, b1);
                    mma16(o[2 * p + 1], a0, a1, a2, a3, b2, b3);
                }
            }
        }

        mbar_arrive(Bar + 16 * slot + 8);   // this thread is done with tile kt's slot
    }

    // ---- write output (accl[0] = l for row ig0, accl[2] = l for row ig1) ----
    const float inv0 = 1.f / accl[0];
    const float inv1 = 1.f / accl[2];
    const size_t base0 = ((size_t)((b * SS + ig0) * HH + h)) * DD;
    const size_t base1 = ((size_t)((b * SS + ig1) * HH + h)) * DD;
    #pragma unroll
    for (int t = 0; t < 16; t++) {
        const int col = 8 * t + 2 * tg;
        *(float2*)&out[base0 + col] = make_float2(o[t][0] * inv0, o[t][1] * inv0);
        *(float2*)&out[base1 + col] = make_float2(o[t][2] * inv1, o[t][3] * inv1);
    }
}

extern "C" void kernel_launch(void* const* d_in, const int* in_sizes, int n_in,
                              void* d_out, int out_size)
{
    const float* q = (const float*)d_in[0];   // query  [4096,32,128]
    const float* k = (const float*)d_in[1];   // key    [4096, 8,128]
    const float* v = (const float*)d_in[2];   // value  [4096, 8,128]
    // d_in[3..5] (caches + block table) do not affect the output: the cache
    // write-then-gather of the same permutation blocks returns key/value unchanged.
    float* out = (float*)d_out;

    convert_kv<<<KV_ELEMS / (256 * 8), 256>>>(k, v);

    cudaFuncSetAttribute(attn_kernel,
                         cudaFuncAttributeMaxDynamicSharedMemorySize,
                         SMEM_BYTES);
    dim3 grid(SS / QTILE, HH, BB);   // 8 x 32 x 4 = 1024 blocks
    attn_kernel<<<grid, NT, SMEM_BYTES>>>(q, out);
}